// round 5
// baseline (speedup 1.0000x reference)
#include <cuda_runtime.h>
#include <cstdint>

#define Bq 256
#define Nn 256
#define Dd 1024
#define Ss 1024
#define NT 16            // n-panel depth
#define MS_PITCH 68      // ms_dup row pitch in floats (bank spread, 16B-aligned)
#define STAGE_FLOATS (2 * NT * Dd)           // 32768
#define MS_OFF STAGE_FLOATS                  // ms_dup at float idx 32768
#define SMEM_FLOATS (MS_OFF + Nn * MS_PITCH) // 50176
#define SMEM_BYTES (SMEM_FLOATS * 4)         // 200704

typedef unsigned long long u64t;

// Scratch (device globals: allowed; no allocation APIs anywhere)
__device__ float g_A[Bq * Ss];           // state @ Q^T   [256,1024]
__device__ float g_M[Bq * Nn];           // A @ K         [256,256]
__device__ float g_ctx_scratch[Bq * Dd]; // fallback ctx if out holds only W

// ---------------------------------------------------------------------------
__global__ void zero_ctx_kernel(float* __restrict__ ctx) {
    int i = blockIdx.x * blockDim.x + threadIdx.x;
    if (i < Bq * Dd) ctx[i] = 0.0f;
}

// ---------------------------------------------------------------------------
// A[b,s] = sum_k state[b,k] * Q[s,k]   (both K-contiguous)
__global__ void gemm_A_kernel(const float* __restrict__ state,
                              const float* __restrict__ Q) {
    __shared__ float sS[32][33];
    __shared__ float sQ[32][33];
    int tx = threadIdx.x, ty = threadIdx.y;
    int t = ty * 16 + tx;
    int b0 = blockIdx.y * 32, s0 = blockIdx.x * 32;
    float acc00 = 0.f, acc01 = 0.f, acc10 = 0.f, acc11 = 0.f;
    for (int k0 = 0; k0 < Ss; k0 += 32) {
        #pragma unroll
        for (int l = t; l < 1024; l += 256) {
            int r = l >> 5, c = l & 31;
            sS[r][c] = state[(b0 + r) * Ss + k0 + c];
            sQ[r][c] = Q[(s0 + r) * Ss + k0 + c];
        }
        __syncthreads();
        #pragma unroll
        for (int kk = 0; kk < 32; kk++) {
            float a0 = sS[2 * ty][kk],     a1 = sS[2 * ty + 1][kk];
            float q0 = sQ[2 * tx][kk],     q1 = sQ[2 * tx + 1][kk];
            acc00 = fmaf(a0, q0, acc00);
            acc01 = fmaf(a0, q1, acc01);
            acc10 = fmaf(a1, q0, acc10);
            acc11 = fmaf(a1, q1, acc11);
        }
        __syncthreads();
    }
    g_A[(b0 + 2 * ty)     * Ss + s0 + 2 * tx]     = acc00;
    g_A[(b0 + 2 * ty)     * Ss + s0 + 2 * tx + 1] = acc01;
    g_A[(b0 + 2 * ty + 1) * Ss + s0 + 2 * tx]     = acc10;
    g_A[(b0 + 2 * ty + 1) * Ss + s0 + 2 * tx + 1] = acc11;
}

// ---------------------------------------------------------------------------
// M[b,n] = sum_s A[b,s] * K[s,n]
__global__ void gemm_M_kernel(const float* __restrict__ Km) {
    __shared__ float sA[32][33];
    __shared__ float sK[32][33];
    int tx = threadIdx.x, ty = threadIdx.y;
    int t = ty * 16 + tx;
    int b0 = blockIdx.y * 32, n0 = blockIdx.x * 32;
    float acc00 = 0.f, acc01 = 0.f, acc10 = 0.f, acc11 = 0.f;
    for (int kc = 0; kc < Ss; kc += 32) {
        #pragma unroll
        for (int l = t; l < 1024; l += 256) {
            int r = l >> 5, c = l & 31;
            sA[r][c] = g_A[(b0 + r) * Ss + kc + c];
            sK[r][c] = Km[(kc + r) * Nn + n0 + c];
        }
        __syncthreads();
        #pragma unroll
        for (int kk = 0; kk < 32; kk++) {
            float a0 = sA[2 * ty][kk],     a1 = sA[2 * ty + 1][kk];
            float b0v = sK[kk][2 * tx],    b1v = sK[kk][2 * tx + 1];
            acc00 = fmaf(a0, b0v, acc00);
            acc01 = fmaf(a0, b1v, acc01);
            acc10 = fmaf(a1, b0v, acc10);
            acc11 = fmaf(a1, b1v, acc11);
        }
        __syncthreads();
    }
    g_M[(b0 + 2 * ty)     * Nn + n0 + 2 * tx]     = acc00;
    g_M[(b0 + 2 * ty)     * Nn + n0 + 2 * tx + 1] = acc01;
    g_M[(b0 + 2 * ty + 1) * Nn + n0 + 2 * tx]     = acc10;
    g_M[(b0 + 2 * ty + 1) * Nn + n0 + 2 * tx + 1] = acc11;
}

// ---------------------------------------------------------------------------
__device__ __forceinline__ void cp_async16(uint32_t saddr, const void* gptr) {
    asm volatile("cp.async.cg.shared.global [%0], [%1], 16;\n"
                 :: "r"(saddr), "l"(gptr));
}
// packed f32x2 helpers (SASS FFMA2 — only reachable via PTX fma.rn.f32x2)
__device__ __forceinline__ u64t pk2(float x, float y) {
    u64t r; asm("mov.b64 %0, {%1, %2};" : "=l"(r) : "f"(x), "f"(y)); return r;
}
__device__ __forceinline__ float2 up2(u64t a) {
    float2 f; asm("mov.b64 {%0, %1}, %2;" : "=f"(f.x), "=f"(f.y) : "l"(a)); return f;
}
__device__ __forceinline__ void fma2(u64t& d, u64t a, u64t b) {
    asm("fma.rn.f32x2 %0, %1, %2, %0;" : "+l"(d) : "l"(a), "l"(b));
}

// ---------------------------------------------------------------------------
// Main fused kernel: one CTA = (i, 32 b-rows), 16 warps.
// Warp w: row-group rg = w>>2 (rows 8rg..8rg+7), d-quarter q = w&3.
// Lane covers d = q*256 + 4*lane + {0..3}  and  + 128.
// Per nn: 4 broadcast LDS.128 (pre-duplicated M pairs) + 2 LDS.128 (v)
// feed 32 FFMA2 — crossbar 12 cyc/warp vs 64 fma cyc/warp.
__global__ void __launch_bounds__(512, 1)
attn_main_kernel(const float* __restrict__ FV,
                 float* __restrict__ Wout,
                 float* __restrict__ ctx) {
    extern __shared__ float smem[];
    float* ms = smem + MS_OFF;            // ms_dup [256 n][68]: (m,m) pairs
    const int i   = blockIdx.y;
    const int gb0 = blockIdx.x * 32;
    const int tid = threadIdx.x;
    const int w = tid >> 5, lane = tid & 31;
    const int rg = w >> 2, q = w & 3;
    const float* FVi = FV + (size_t)i * Nn * Dd;
    const uint32_t sbase = (uint32_t)__cvta_generic_to_shared(smem);

    // Preload panel 0 (FV[i, 0:NT, :]) — overlap with ms_dup build
    {
        const float4* src = (const float4*)FVi;
        #pragma unroll
        for (int k = 0; k < 8; k++)
            cp_async16(sbase + (uint32_t)(tid + k * 512) * 16, src + tid + k * 512);
        asm volatile("cp.async.commit_group;\n");
    }

    // Build duplicated transposed M: ms[n*68 + 2r] = ms[..+1] = M[gb0+r, n]
    #pragma unroll
    for (int u = tid; u < 32 * Nn; u += 512) {
        int r = u >> 8, n = u & 255;            // coalesced g_M read over n
        float v = g_M[(size_t)(gb0 + r) * Nn + n];
        *reinterpret_cast<float2*>(&ms[n * MS_PITCH + 2 * r]) = make_float2(v, v);
    }

    u64t acc[8][4];
    #pragma unroll
    for (int r = 0; r < 8; r++)
        #pragma unroll
        for (int jp = 0; jp < 4; jp++) acc[r][jp] = 0ull;

    const int dbase = q * 256 + 4 * lane;       // first float4 chunk; second at +128

    for (int t = 0; t < Nn / NT; t++) {
        const float* cur = smem + (t & 1) * NT * Dd;
        if (t + 1 < Nn / NT) {
            uint32_t dst = sbase + (uint32_t)(((t + 1) & 1) * NT * Dd) * 4u;
            const float4* src = (const float4*)(FVi + (size_t)(t + 1) * NT * Dd);
            #pragma unroll
            for (int k = 0; k < 8; k++)
                cp_async16(dst + (uint32_t)(tid + k * 512) * 16, src + tid + k * 512);
            asm volatile("cp.async.commit_group;\n");
            asm volatile("cp.async.wait_group 1;\n");
        } else {
            asm volatile("cp.async.wait_group 0;\n");
        }
        __syncthreads();

        const float* mrow = ms + (t * NT) * MS_PITCH + 16 * rg;
        #pragma unroll 4
        for (int nn = 0; nn < NT; nn++) {
            float4 ma = *(const float4*)(mrow + nn * MS_PITCH);       // rows 0,1 (dup)
            float4 mb = *(const float4*)(mrow + nn * MS_PITCH + 4);   // rows 2,3
            float4 mc = *(const float4*)(mrow + nn * MS_PITCH + 8);   // rows 4,5
            float4 md = *(const float4*)(mrow + nn * MS_PITCH + 12);  // rows 6,7
            const float* vrow = cur + nn * Dd + dbase;
            float4 va = *(const float4*)vrow;
            float4 vb = *(const float4*)(vrow + 128);
            u64t v0 = reinterpret_cast<const u64t*>(&va)[0];
            u64t v1 = reinterpret_cast<const u64t*>(&va)[1];
            u64t v2 = reinterpret_cast<const u64t*>(&vb)[0];
            u64t v3 = reinterpret_cast<const u64t*>(&vb)[1];
            u64t m[8];
            m[0] = reinterpret_cast<const u64t*>(&ma)[0];
            m[1] = reinterpret_cast<const u64t*>(&ma)[1];
            m[2] = reinterpret_cast<const u64t*>(&mb)[0];
            m[3] = reinterpret_cast<const u64t*>(&mb)[1];
            m[4] = reinterpret_cast<const u64t*>(&mc)[0];
            m[5] = reinterpret_cast<const u64t*>(&mc)[1];
            m[6] = reinterpret_cast<const u64t*>(&md)[0];
            m[7] = reinterpret_cast<const u64t*>(&md)[1];
            #pragma unroll
            for (int r = 0; r < 8; r++) {
                fma2(acc[r][0], m[r], v0);
                fma2(acc[r][1], m[r], v1);
                fma2(acc[r][2], m[r], v2);
                fma2(acc[r][3], m[r], v3);
            }
        }
        __syncthreads();
    }

    // ---- softmax over full D row (row split across 4 d-quarter warps)
    float* ctxs = smem;            // [4 rg][1024] context partials (stage dead)
    float* red  = smem + 4096;     // [0:128) partial max, [128:256) partial sum

    float mx[8];
    #pragma unroll
    for (int r = 0; r < 8; r++) {
        float2 f0 = up2(acc[r][0]), f1 = up2(acc[r][1]);
        float2 f2 = up2(acc[r][2]), f3 = up2(acc[r][3]);
        float mm = fmaxf(fmaxf(fmaxf(f0.x, f0.y), fmaxf(f1.x, f1.y)),
                         fmaxf(fmaxf(f2.x, f2.y), fmaxf(f3.x, f3.y)));
        #pragma unroll
        for (int off = 16; off; off >>= 1)
            mm = fmaxf(mm, __shfl_xor_sync(0xffffffffu, mm, off));
        mx[r] = mm;
    }
    if (lane == 0) {
        #pragma unroll
        for (int r = 0; r < 8; r++) red[q * 32 + rg * 8 + r] = mx[r];
    }
    __syncthreads();
    #pragma unroll
    for (int r = 0; r < 8; r++) {
        int idx = rg * 8 + r;
        mx[r] = fmaxf(fmaxf(red[idx], red[32 + idx]),
                      fmaxf(red[64 + idx], red[96 + idx]));
    }
    float sm[8];
    #pragma unroll
    for (int r = 0; r < 8; r++) {
        float s = 0.f;
        #pragma unroll
        for (int jp = 0; jp < 4; jp++) {
            float2 f = up2(acc[r][jp]);
            f.x = __expf(f.x - mx[r]);
            f.y = __expf(f.y - mx[r]);
            s += f.x + f.y;
            acc[r][jp] = pk2(f.x, f.y);
        }
        #pragma unroll
        for (int off = 16; off; off >>= 1)
            s += __shfl_xor_sync(0xffffffffu, s, off);
        sm[r] = s;
    }
    __syncthreads();   // red reused: ensure max phase fully consumed
    if (lane == 0) {
        #pragma unroll
        for (int r = 0; r < 8; r++) red[128 + q * 32 + rg * 8 + r] = sm[r];
    }
    __syncthreads();
    #pragma unroll
    for (int r = 0; r < 8; r++) {
        int idx = 128 + rg * 8 + r;
        sm[r] = (red[idx] + red[32 + idx]) + (red[64 + idx] + red[96 + idx]);
    }

    // ---- W store + context partial
    float inv[8];
    #pragma unroll
    for (int r = 0; r < 8; r++) inv[r] = 1.f / sm[r];

    float4 ca = make_float4(0.f, 0.f, 0.f, 0.f);
    float4 cb = make_float4(0.f, 0.f, 0.f, 0.f);

    const int growb = gb0 + 8 * rg;
    #pragma unroll
    for (int r = 0; r < 8; r++) {
        const int grow = growb + r;
        float* wr = Wout + ((size_t)i * Bq + grow) * Dd + dbase;
        const float* fr = FVi + (size_t)grow * Dd + dbase;
        float2 e0 = up2(acc[r][0]), e1 = up2(acc[r][1]);
        float2 e2 = up2(acc[r][2]), e3 = up2(acc[r][3]);
        float4 wa = make_float4(e0.x * inv[r], e0.y * inv[r],
                                e1.x * inv[r], e1.y * inv[r]);
        float4 wb = make_float4(e2.x * inv[r], e2.y * inv[r],
                                e3.x * inv[r], e3.y * inv[r]);
        *reinterpret_cast<float4*>(wr)       = wa;
        *reinterpret_cast<float4*>(wr + 128) = wb;
        float4 fa = *reinterpret_cast<const float4*>(fr);
        float4 fb = *reinterpret_cast<const float4*>(fr + 128);
        ca.x = fmaf(wa.x, fa.x, ca.x); ca.y = fmaf(wa.y, fa.y, ca.y);
        ca.z = fmaf(wa.z, fa.z, ca.z); ca.w = fmaf(wa.w, fa.w, ca.w);
        cb.x = fmaf(wb.x, fb.x, cb.x); cb.y = fmaf(wb.y, fb.y, cb.y);
        cb.z = fmaf(wb.z, fb.z, cb.z); cb.w = fmaf(wb.w, fb.w, cb.w);
    }
    *reinterpret_cast<float4*>(&ctxs[rg * Dd + dbase])       = ca;
    *reinterpret_cast<float4*>(&ctxs[rg * Dd + dbase + 128]) = cb;
    __syncthreads();
    if (rg == 0) {
        #pragma unroll
        for (int half = 0; half < 2; half++) {
            int d = dbase + 128 * half;
            float4 s0 = *reinterpret_cast<float4*>(&ctxs[d]);
            float4 s1 = *reinterpret_cast<float4*>(&ctxs[Dd + d]);
            float4 s2 = *reinterpret_cast<float4*>(&ctxs[2 * Dd + d]);
            float4 s3 = *reinterpret_cast<float4*>(&ctxs[3 * Dd + d]);
            atomicAdd(&ctx[(size_t)i * Dd + d],     (s0.x + s1.x) + (s2.x + s3.x));
            atomicAdd(&ctx[(size_t)i * Dd + d + 1], (s0.y + s1.y) + (s2.y + s3.y));
            atomicAdd(&ctx[(size_t)i * Dd + d + 2], (s0.z + s1.z) + (s2.z + s3.z));
            atomicAdd(&ctx[(size_t)i * Dd + d + 3], (s0.w + s1.w) + (s2.w + s3.w));
        }
    }
}

// ---------------------------------------------------------------------------
extern "C" void kernel_launch(void* const* d_in, const int* in_sizes, int n_in,
                              void* d_out, int out_size) {
    const float* FV    = (const float*)d_in[0];
    const float* state = (const float*)d_in[1];
    const float* Q     = (const float*)d_in[2];
    const float* Km    = (const float*)d_in[3];
    float* out = (float*)d_out;

    // Output layout: (context [B,D], W [B,B,D]) concatenated. If the harness
    // sized d_out for W only, keep context in device scratch instead.
    const long long wsz = (long long)Bq * Bq * Dd;
    float* ctxp;
    float* Wp;
    if ((long long)out_size == wsz) {
        Wp = out;
        cudaGetSymbolAddress((void**)&ctxp, g_ctx_scratch);
    } else {
        ctxp = out;
        Wp   = out + (size_t)Bq * Dd;
    }

    cudaFuncSetAttribute(attn_main_kernel,
                         cudaFuncAttributeMaxDynamicSharedMemorySize, SMEM_BYTES);

    zero_ctx_kernel<<<(Bq * Dd + 511) / 512, 512>>>(ctxp);
    gemm_A_kernel<<<dim3(Ss / 32, Bq / 32), dim3(16, 16)>>>(state, Q);
    gemm_M_kernel<<<dim3(Nn / 32, Bq / 32), dim3(16, 16)>>>(Km);
    attn_main_kernel<<<dim3(Bq / 32, Bq), 512, SMEM_BYTES>>>(FV, Wp, ctxp);
}

// round 7
// speedup vs baseline: 1.1102x; 1.1102x over previous
#include <cuda_runtime.h>
#include <cstdint>

#define Bq 256
#define Nn 256
#define Dd 1024
#define Ss 1024

// K1 tiling
#define STG_P 132                      // fp32 stage pitch
#define OFF_STAGE 0
#define STAGE_F (2 * 32 * STG_P)       // 8448 floats (double-buffered chunk)
#define OFF_BFH STAGE_F                // B frags hi: 4 ks * 8 jp * 32 * 4 = 4096
#define OFF_BFL (OFF_BFH + 4096)
#define OFF_RED (OFF_BFL + 4096)       // fm[128] + redm[4][128] + reds[4][128]
#define SMEM_F (OFF_RED + 1152)
#define SMEM_BYTES (SMEM_F * 4)        // 71168 B

// Scratch (device globals — no allocation APIs anywhere)
__device__ float    g_A[Bq * Ss];
__device__ float    g_M[Bq * Nn];
__device__ uint32_t g_Ahi[Bq * Nn];       // A fragments, tf32 hi
__device__ uint32_t g_Alo[Bq * Nn];       // A fragments, tf32 lo
__device__ float    g_stats[Bq * Bq * 16]; // per (i,b,nt 0..7): m, s
__device__ float    g_ctx_scratch[Bq * Dd];

// ---------------------------------------------------------------------------
__global__ void gemm_A_kernel(const float* __restrict__ state,
                              const float* __restrict__ Q) {
    __shared__ float sS[32][33];
    __shared__ float sQ[32][33];
    int tx = threadIdx.x, ty = threadIdx.y;
    int t = ty * 16 + tx;
    int b0 = blockIdx.y * 32, s0 = blockIdx.x * 32;
    float acc00 = 0.f, acc01 = 0.f, acc10 = 0.f, acc11 = 0.f;
    for (int k0 = 0; k0 < Ss; k0 += 32) {
        #pragma unroll
        for (int l = t; l < 1024; l += 256) {
            int r = l >> 5, c = l & 31;
            sS[r][c] = state[(b0 + r) * Ss + k0 + c];
            sQ[r][c] = Q[(s0 + r) * Ss + k0 + c];
        }
        __syncthreads();
        #pragma unroll
        for (int kk = 0; kk < 32; kk++) {
            float a0 = sS[2 * ty][kk],     a1 = sS[2 * ty + 1][kk];
            float q0 = sQ[2 * tx][kk],     q1 = sQ[2 * tx + 1][kk];
            acc00 = fmaf(a0, q0, acc00);
            acc01 = fmaf(a0, q1, acc01);
            acc10 = fmaf(a1, q0, acc10);
            acc11 = fmaf(a1, q1, acc11);
        }
        __syncthreads();
    }
    g_A[(b0 + 2 * ty)     * Ss + s0 + 2 * tx]     = acc00;
    g_A[(b0 + 2 * ty)     * Ss + s0 + 2 * tx + 1] = acc01;
    g_A[(b0 + 2 * ty + 1) * Ss + s0 + 2 * tx]     = acc10;
    g_A[(b0 + 2 * ty + 1) * Ss + s0 + 2 * tx + 1] = acc11;
}

__global__ void gemm_M_kernel(const float* __restrict__ Km) {
    __shared__ float sA[32][33];
    __shared__ float sK[32][33];
    int tx = threadIdx.x, ty = threadIdx.y;
    int t = ty * 16 + tx;
    int b0 = blockIdx.y * 32, n0 = blockIdx.x * 32;
    float acc00 = 0.f, acc01 = 0.f, acc10 = 0.f, acc11 = 0.f;
    for (int kc = 0; kc < Ss; kc += 32) {
        #pragma unroll
        for (int l = t; l < 1024; l += 256) {
            int r = l >> 5, c = l & 31;
            sA[r][c] = g_A[(b0 + r) * Ss + kc + c];
            sK[r][c] = Km[(kc + r) * Nn + n0 + c];
        }
        __syncthreads();
        #pragma unroll
        for (int kk = 0; kk < 32; kk++) {
            float a0 = sA[2 * ty][kk],     a1 = sA[2 * ty + 1][kk];
            float b0v = sK[kk][2 * tx],    b1v = sK[kk][2 * tx + 1];
            acc00 = fmaf(a0, b0v, acc00);
            acc01 = fmaf(a0, b1v, acc01);
            acc10 = fmaf(a1, b0v, acc10);
            acc11 = fmaf(a1, b1v, acc11);
        }
        __syncthreads();
    }
    g_M[(b0 + 2 * ty)     * Nn + n0 + 2 * tx]     = acc00;
    g_M[(b0 + 2 * ty)     * Nn + n0 + 2 * tx + 1] = acc01;
    g_M[(b0 + 2 * ty + 1) * Nn + n0 + 2 * tx]     = acc10;
    g_M[(b0 + 2 * ty + 1) * Nn + n0 + 2 * tx + 1] = acc11;
}

// ---------------------------------------------------------------------------
__device__ __forceinline__ void cp_async16(uint32_t saddr, const void* gptr) {
    asm volatile("cp.async.cg.shared.global [%0], [%1], 16;\n"
                 :: "r"(saddr), "l"(gptr));
}
__device__ __forceinline__ uint32_t f2tf(float x) {
    uint32_t r;
    asm("cvt.rna.tf32.f32 %0, %1;" : "=r"(r) : "f"(x));
    return r;
}
__device__ __forceinline__ void tfsplit(float x, uint32_t& hi, uint32_t& lo) {
    hi = f2tf(x);
    lo = f2tf(x - __uint_as_float(hi));
}
__device__ __forceinline__ void mma_tf32(float* c, const uint32_t* a,
                                         uint32_t b0, uint32_t b1) {
    asm volatile(
        "mma.sync.aligned.m16n8k8.row.col.f32.tf32.tf32.f32 "
        "{%0,%1,%2,%3}, {%4,%5,%6,%7}, {%8,%9}, {%0,%1,%2,%3};"
        : "+f"(c[0]), "+f"(c[1]), "+f"(c[2]), "+f"(c[3])
        : "r"(a[0]), "r"(a[1]), "r"(a[2]), "r"(a[3]), "r"(b0), "r"(b1));
}

// ---------------------------------------------------------------------------
// A pre-split: g_M -> tf32 hi/lo in mma fragment order.
// Frag (kg, mt): lane l holds a0=(m=mt*16+l/4, k=kg*8+l%4), a1=m+8, a2=k+4, a3=both.
__global__ void afrag_kernel() {
    int wg = blockIdx.x * 8 + (threadIdx.x >> 5);   // 0..511 = kg*16 + mt
    int l  = threadIdx.x & 31;
    int m0 = (wg & 15) * 16 + (l >> 2);
    int k0 = (wg >> 4) * 8 + (l & 3);
    float x0 = g_M[m0 * Nn + k0];
    float x1 = g_M[(m0 + 8) * Nn + k0];
    float x2 = g_M[m0 * Nn + k0 + 4];
    float x3 = g_M[(m0 + 8) * Nn + k0 + 4];
    uint4 h, lo;
    tfsplit(x0, h.x, lo.x); tfsplit(x1, h.y, lo.y);
    tfsplit(x2, h.z, lo.z); tfsplit(x3, h.w, lo.w);
    *(uint4*)(g_Ahi + (size_t)(wg * 32 + l) * 4) = h;
    *(uint4*)(g_Alo + (size_t)(wg * 32 + l) * 4) = lo;
}

// ---------------------------------------------------------------------------
// K1: 3-pass tf32 mma.sync GEMM. CTA=(nt,mt,i): C[128 m][128 d], k=256 (8x32).
// 16 warps as 4m x 4n, warp tile 32x32. Writes pre-softmax W + per-tile stats.
__global__ void __launch_bounds__(512, 1)
wpre_mma_kernel(const float* __restrict__ FV, float* __restrict__ Wout) {
    extern __shared__ float smem[];
    uint32_t* smu = (uint32_t*)smem;
    const int i  = blockIdx.z;
    const int mt = blockIdx.y;
    const int nt = blockIdx.x;
    const int b0 = mt * 128;
    const int d0 = nt * 128;
    const int tid = threadIdx.x;
    const int w = tid >> 5, l = tid & 31;
    const int mw = w & 3, nw = w >> 2;          // mma warp grid
    const int cks = w >> 2, cjp = (w & 3) * 2;  // conversion assignment
    const float* FVi = FV + (size_t)i * Nn * Dd;
    const uint32_t sbase = (uint32_t)__cvta_generic_to_shared(smem);

    // prologue: stage chunk 0 (FV[i, 0:32, d0:d0+128])
    #pragma unroll
    for (int k = 0; k < 2; k++) {
        int v = tid + 512 * k;                  // 1024 float4
        int r = v >> 5, c4 = v & 31;
        cp_async16(sbase + (uint32_t)(r * STG_P + c4 * 4) * 4,
                   FVi + (size_t)r * Dd + d0 + c4 * 4);
    }
    asm volatile("cp.async.commit_group;\n");

    float acc[2][4][4];
    #pragma unroll
    for (int a = 0; a < 2; a++)
        #pragma unroll
        for (int b = 0; b < 4; b++)
            #pragma unroll
            for (int c = 0; c < 4; c++) acc[a][b][c] = 0.f;

    for (int c = 0; c < 8; c++) {
        if (c + 1 < 8) {
            const float* src = FVi + (size_t)(c + 1) * 32 * Dd + d0;
            uint32_t dst = sbase + (uint32_t)(((c + 1) & 1) * 32 * STG_P) * 4;
            #pragma unroll
            for (int k = 0; k < 2; k++) {
                int v = tid + 512 * k;
                int r = v >> 5, c4 = v & 31;
                cp_async16(dst + (uint32_t)(r * STG_P + c4 * 4) * 4,
                           src + (size_t)r * Dd + c4 * 4);
            }
            asm volatile("cp.async.commit_group;\n");
            asm volatile("cp.async.wait_group 1;\n");
        } else {
            asm volatile("cp.async.wait_group 0;\n");
        }
        __syncthreads();

        // convert B chunk -> fragment-ordered tf32 hi/lo
        const float* stg = smem + (c & 1) * 32 * STG_P;
        #pragma unroll
        for (int jj = 0; jj < 2; jj++) {
            int jp = cjp + jj;
            uint4 h, lo;
            #pragma unroll
            for (int sub = 0; sub < 4; sub++) {
                int j = jp * 2 + (sub >> 1);
                int r = sub & 1;
                int k = cks * 8 + r * 4 + (l & 3);
                int d = j * 8 + (l >> 2);
                float x = stg[k * STG_P + d];
                tfsplit(x, ((uint32_t*)&h)[sub], ((uint32_t*)&lo)[sub]);
            }
            int word = ((cks * 8 + jp) * 32 + l) * 4;
            *(uint4*)(smu + OFF_BFH + word) = h;
            *(uint4*)(smu + OFF_BFL + word) = lo;
        }
        __syncthreads();

        // mma over 4 k-steps of 8
        #pragma unroll
        for (int ks = 0; ks < 4; ks++) {
            const int kg = c * 4 + ks;
            uint4 ah[2], al[2];
            #pragma unroll
            for (int mi = 0; mi < 2; mi++) {
                int mtile = mt * 8 + mw * 2 + mi;
                size_t aw = (size_t)((kg * 16 + mtile) * 32 + l) * 4;
                ah[mi] = *(const uint4*)(g_Ahi + aw);
                al[mi] = *(const uint4*)(g_Alo + aw);
            }
            uint4 bh[2], bl[2];
            #pragma unroll
            for (int p = 0; p < 2; p++) {
                int word = ((ks * 8 + nw * 2 + p) * 32 + l) * 4;
                bh[p] = *(const uint4*)(smu + OFF_BFH + word);
                bl[p] = *(const uint4*)(smu + OFF_BFL + word);
            }
            #pragma unroll
            for (int mi = 0; mi < 2; mi++) {
                #pragma unroll
                for (int j = 0; j < 4; j++) {
                    int p = j >> 1, hf = j & 1;
                    uint32_t bh0 = hf ? bh[p].z : bh[p].x;
                    uint32_t bh1 = hf ? bh[p].w : bh[p].y;
                    uint32_t bl0 = hf ? bl[p].z : bl[p].x;
                    uint32_t bl1 = hf ? bl[p].w : bl[p].y;
                    mma_tf32(acc[mi][j], (const uint32_t*)&ah[mi], bh0, bh1);
                    mma_tf32(acc[mi][j], (const uint32_t*)&ah[mi], bl0, bl1);
                    mma_tf32(acc[mi][j], (const uint32_t*)&al[mi], bh0, bh1);
                }
            }
        }
        __syncthreads();
    }

    // ---- epilogue: per-row tile stats + pre-softmax W store
    float* fm   = smem + OFF_RED;        // [128]
    float* redm = fm + 128;              // [4][128]
    float* reds = redm + 512;            // [4][128]

    // per-lane row max (rows: mw*32 + mi*16 + (l>>2) + 8h)
    #pragma unroll
    for (int mi = 0; mi < 2; mi++) {
        #pragma unroll
        for (int h = 0; h < 2; h++) {
            float m = -3.4e38f;
            #pragma unroll
            for (int j = 0; j < 4; j++)
                m = fmaxf(m, fmaxf(acc[mi][j][2 * h], acc[mi][j][2 * h + 1]));
            m = fmaxf(m, __shfl_xor_sync(0xffffffffu, m, 1));
            m = fmaxf(m, __shfl_xor_sync(0xffffffffu, m, 2));
            if ((l & 3) == 0)
                redm[nw * 128 + mw * 32 + mi * 16 + (l >> 2) + 8 * h] = m;
        }
    }
    __syncthreads();
    if (tid < 128)
        fm[tid] = fmaxf(fmaxf(redm[tid], redm[128 + tid]),
                        fmaxf(redm[256 + tid], redm[384 + tid]));
    __syncthreads();
    #pragma unroll
    for (int mi = 0; mi < 2; mi++) {
        #pragma unroll
        for (int h = 0; h < 2; h++) {
            int row = mw * 32 + mi * 16 + (l >> 2) + 8 * h;
            float m = fm[row];
            float s = 0.f;
            #pragma unroll
            for (int j = 0; j < 4; j++)
                s += __expf(acc[mi][j][2 * h] - m) + __expf(acc[mi][j][2 * h + 1] - m);
            s += __shfl_xor_sync(0xffffffffu, s, 1);
            s += __shfl_xor_sync(0xffffffffu, s, 2);
            if ((l & 3) == 0) reds[nw * 128 + row] = s;
        }
    }
    __syncthreads();
    if (tid < 128) {
        int sidx = (((i * Bq) + b0 + tid) * 8 + nt) * 2;
        g_stats[sidx]     = fm[tid];
        g_stats[sidx + 1] = (reds[tid] + reds[128 + tid])
                          + (reds[256 + tid] + reds[384 + tid]);
    }
    // raw logits store (STG.64, 32B segments)
    #pragma unroll
    for (int mi = 0; mi < 2; mi++) {
        #pragma unroll
        for (int h = 0; h < 2; h++) {
            int row = mw * 32 + mi * 16 + (l >> 2) + 8 * h;
            float* wr = Wout + ((size_t)i * Bq + b0 + row) * Dd
                      + d0 + nw * 32 + 2 * (l & 3);
            #pragma unroll
            for (int j = 0; j < 4; j++)
                *(float2*)(wr + j * 8) =
                    make_float2(acc[mi][j][2 * h], acc[mi][j][2 * h + 1]);
        }
    }
}

// ---------------------------------------------------------------------------
// K2: combine 8 tile-stats per row, softmax W in place, accumulate context.
__global__ void __launch_bounds__(512, 2)
softmax_ctx_kernel(const float* __restrict__ FV,
                   float* __restrict__ W,
                   float* __restrict__ ctx) {
    __shared__ float sm_m[256], sm_inv[256];
    const int i = blockIdx.y;
    const int d = blockIdx.x * 512 + threadIdx.x;
    if (threadIdx.x < 256) {
        int b = threadIdx.x;
        const float* st = g_stats + (size_t)(i * Bq + b) * 16;
        float m = st[0];
        #pragma unroll
        for (int t = 1; t < 8; t++) m = fmaxf(m, st[2 * t]);
        float s = 0.f;
        #pragma unroll
        for (int t = 0; t < 8; t++) s += st[2 * t + 1] * __expf(st[2 * t] - m);
        sm_m[b] = m;
        sm_inv[b] = 1.f / s;
    }
    __syncthreads();
    float acc = 0.f;
    const float* FVi = FV + (size_t)i * Nn * Dd + d;
    float* Wi = W + (size_t)i * Bq * Dd + d;
    #pragma unroll 4
    for (int b = 0; b < Bq; b++) {
        float x = Wi[(size_t)b * Dd];
        float w = __expf(x - sm_m[b]) * sm_inv[b];
        Wi[(size_t)b * Dd] = w;
        acc = fmaf(w, FVi[(size_t)b * Dd], acc);
    }
    ctx[(size_t)i * Dd + d] = acc;
}

// ---------------------------------------------------------------------------
extern "C" void kernel_launch(void* const* d_in, const int* in_sizes, int n_in,
                              void* d_out, int out_size) {
    const float* FV    = (const float*)d_in[0];
    const float* state = (const float*)d_in[1];
    const float* Q     = (const float*)d_in[2];
    const float* Km    = (const float*)d_in[3];
    float* out = (float*)d_out;

    const long long wsz = (long long)Bq * Bq * Dd;
    float* ctxp;
    float* Wp;
    if ((long long)out_size == wsz) {
        Wp = out;
        cudaGetSymbolAddress((void**)&ctxp, g_ctx_scratch);
    } else {
        ctxp = out;
        Wp   = out + (size_t)Bq * Dd;
    }

    cudaFuncSetAttribute(wpre_mma_kernel,
                         cudaFuncAttributeMaxDynamicSharedMemorySize, SMEM_BYTES);

    gemm_A_kernel<<<dim3(Ss / 32, Bq / 32), dim3(16, 16)>>>(state, Q);
    gemm_M_kernel<<<dim3(Nn / 32, Bq / 32), dim3(16, 16)>>>(Km);
    afrag_kernel<<<64, 256>>>();
    wpre_mma_kernel<<<dim3(8, 2, 256), 512, SMEM_BYTES>>>(FV, Wp);
    softmax_ctx_kernel<<<dim3(2, 256), 512>>>(FV, Wp, ctxp);
}